// round 11
// baseline (speedup 1.0000x reference)
#include <cuda_runtime.h>
#include <cuda_bf16.h>
#include <cstdint>

typedef unsigned long long ull;

#define BATCH 4
#define NC    64
#define CI    32
#define NPIX  6400
#define BM    64           // q rows per CTA
#define BN    64           // k cols per tile
#define NT    (NPIX / BN)  // 100 k-tiles
#define LOG2E 1.4426950408889634f

// ---------------- scratch (__device__ globals; no allocs allowed) ----------
__device__ __align__(1024) __nv_bfloat16 g_tqn[BATCH * NPIX * 64]; // theta*log2e: [b][n][hi32|lo32]
__device__ __align__(1024) __nv_bfloat16 g_pqn[BATCH * NPIX * 64]; // phi:         [b][n][hi32|lo32]
__device__ __align__(1024) __nv_bfloat16 g_gxh[BATCH * CI * NPIX]; // g hi:  [b][d][n]
__device__ __align__(1024) __nv_bfloat16 g_gxl[BATCH * CI * NPIX]; // g lo:  [b][d][n]
__device__ float g_y[BATCH * CI * NPIX];                           // attention out [b][d][n]

// ---------------- small helpers -------------------------------------------
__device__ __forceinline__ ull ffma2(ull a, ull b, ull c) {
    ull d; asm("fma.rn.f32x2 %0, %1, %2, %3;" : "=l"(d) : "l"(a), "l"(b), "l"(c)); return d;
}
__device__ __forceinline__ ull pack2(float lo, float hi) {
    ull d; asm("mov.b64 %0, {%1, %2};" : "=l"(d) : "f"(lo), "f"(hi)); return d;
}
__device__ __forceinline__ void unpack2(ull v, float& lo, float& hi) {
    asm("mov.b64 {%0, %1}, %2;" : "=f"(lo), "=f"(hi) : "l"(v));
}
// packed bf16x2: low half <- lo, high half <- hi
__device__ __forceinline__ uint32_t bf16x2(float lo, float hi) {
    uint32_t r; asm("cvt.rn.bf16x2.f32 %0, %1, %2;" : "=r"(r) : "f"(hi), "f"(lo)); return r;
}
__device__ __forceinline__ float ex2(float x) {
    float r; asm("ex2.approx.f32 %0, %1;" : "=f"(r) : "f"(x)); return r;
}
__device__ __forceinline__ uint32_t sptr(const void* p) {
    return (uint32_t)__cvta_generic_to_shared(p);
}
__device__ __forceinline__ void cpa16(uint32_t dst, const void* src) {
    asm volatile("cp.async.cg.shared.global [%0], [%1], 16;" :: "r"(dst), "l"(src));
}
__device__ __forceinline__ void cpa_commit() { asm volatile("cp.async.commit_group;" ::: "memory"); }
__device__ __forceinline__ void cpa_wait0()  { asm volatile("cp.async.wait_group 0;"  ::: "memory"); }
__device__ __forceinline__ uint32_t sw(uint32_t o) { return o ^ ((o >> 3) & 0x70); } // SW128

// ldmatrix x4 (16-bit tiles, non-transposed)
__device__ __forceinline__ void ldsm4(uint32_t* r, uint32_t addr) {
    asm volatile("ldmatrix.sync.aligned.m8n8.x4.shared.b16 {%0,%1,%2,%3}, [%4];"
                 : "=r"(r[0]), "=r"(r[1]), "=r"(r[2]), "=r"(r[3]) : "r"(addr));
}
// bf16 HMMA: D(16x8,f32) += A(16x16,bf16) * B(16x8,bf16)
__device__ __forceinline__ void mma16816(float* d, const uint32_t* a,
                                         uint32_t b0, uint32_t b1) {
    asm volatile(
        "mma.sync.aligned.m16n8k16.row.col.f32.bf16.bf16.f32 "
        "{%0,%1,%2,%3}, {%4,%5,%6,%7}, {%8,%9}, {%0,%1,%2,%3};"
        : "+f"(d[0]), "+f"(d[1]), "+f"(d[2]), "+f"(d[3])
        : "r"(a[0]), "r"(a[1]), "r"(a[2]), "r"(a[3]), "r"(b0), "r"(b1));
}

// ---------------- SMEM map (BM=64) -----------------------------------------
#define SM_Q    0u       // 64 rows x 128B (hi|lo)                 8192
#define SM_K0   8192u    // 64 x 128B per buf, stride 8192        16384 (x2)
#define SM_VH0  24576u   // 32 x 128B per buf, stride 8192
#define SM_VL0  28672u   //   (vh 4K + vl 4K per buf)             16384 (x2)
#define SM_MISC 40960u   // larr: 2 x 64 floats = 512B
#define SMEM_TOTAL (40960 + 512)
// epilogue reuses SM_K0..SM_K0+16KB as os[2][32][64] floats

// ============================================================================
// Kernel 1: 1x1 convs -> bf16 hi/lo. grid (200, 3): blockIdx.y = which conv.
// theta scaled by log2(e) so softmax uses bare ex2. theta/phi stored as
// [n][hi32|lo32] 128B rows (MMA operand layout); g as d-major hi/lo planes.
// ============================================================================
__global__ void __launch_bounds__(128) front_kernel(
    const float* __restrict__ x,
    const float* __restrict__ wt, const float* __restrict__ bt,
    const float* __restrict__ wp, const float* __restrict__ bp,
    const float* __restrict__ wg, const float* __restrict__ bg)
{
    __shared__ float ws[CI][NC];
    __shared__ float bs[CI];
    int tid = threadIdx.x;
    int m = blockIdx.y;
    const float* wsrc = (m == 0) ? wt : ((m == 1) ? wp : wg);
    const float* bsrc = (m == 0) ? bt : ((m == 1) ? bp : bg);
    float scale = (m == 0) ? LOG2E : 1.0f;
    for (int i = tid; i < CI * NC; i += 128)
        ws[i / NC][i % NC] = wsrc[i] * scale;
    if (tid < CI) bs[tid] = bsrc[tid] * scale;
    __syncthreads();

    int gn = blockIdx.x * 128 + tid;
    int b = gn / NPIX, n = gn % NPIX;

    ull xr2[NC / 2];
#pragma unroll
    for (int c2 = 0; c2 < NC / 2; c2++) {
        float a = x[(b * NC + 2 * c2)     * NPIX + n];
        float c = x[(b * NC + 2 * c2 + 1) * NPIX + n];
        xr2[c2] = pack2(a, c);
    }

    float v[CI];
#pragma unroll
    for (int o = 0; o < CI; o++) {
        const ull* wrow = (const ull*)&ws[o][0];
        ull acc2 = 0ull;
#pragma unroll
        for (int c2 = 0; c2 < NC / 2; c2++) acc2 = ffma2(wrow[c2], xr2[c2], acc2);
        float hi, lo; unpack2(acc2, lo, hi);
        v[o] = bs[o] + lo + hi;
    }

    if (m < 2) {
        uint32_t row[32];
#pragma unroll
        for (int o2 = 0; o2 < 16; o2++) {
            float a = v[2 * o2], c = v[2 * o2 + 1];
            uint32_t hp = bf16x2(a, c);
            row[o2] = hp;
            float ha = __uint_as_float(hp << 16);
            float hc = __uint_as_float(hp & 0xffff0000u);
            row[16 + o2] = bf16x2(a - ha, c - hc);
        }
        __nv_bfloat16* dst = ((m == 0) ? g_tqn : g_pqn) + (size_t)(b * NPIX + n) * 64;
        uint4* d4 = (uint4*)dst;
#pragma unroll
        for (int q = 0; q < 8; q++)
            d4[q] = make_uint4(row[4 * q], row[4 * q + 1], row[4 * q + 2], row[4 * q + 3]);
    } else {
#pragma unroll
        for (int o = 0; o < CI; o++) {
            __nv_bfloat16 h = __float2bfloat16(v[o]);
            size_t idx = (size_t)(b * CI + o) * NPIX + n;
            g_gxh[idx] = h;
            g_gxl[idx] = __float2bfloat16(v[o] - __bfloat162float(h));
        }
    }
}

// ---------------- K/V tile loader (cp.async, SW128 dst, 128 threads) -------
__device__ __forceinline__ void load_kv(uint32_t sb, int buf,
                                        const __nv_bfloat16* pq,
                                        const __nv_bfloat16* vh,
                                        const __nv_bfloat16* vl,
                                        int c0, int tid)
{
    uint32_t kbase = sb + SM_K0 + (uint32_t)buf * 8192u;
#pragma unroll
    for (int h = 0; h < 4; h++) {
        int id = tid + h * 128;
        int k = id >> 3, ch = id & 7;
        cpa16(kbase + sw((uint32_t)(k * 128 + ch * 16)),
              pq + (size_t)(c0 + k) * 64 + ch * 8);
    }
#pragma unroll
    for (int h = 0; h < 2; h++) {
        int id = tid + h * 128;
        int d = id >> 3, ch = id & 7;
        uint32_t voff = sw((uint32_t)(d * 128 + ch * 16));
        cpa16(sb + SM_VH0 + (uint32_t)buf * 8192u + voff, vh + (size_t)d * NPIX + c0 + ch * 8);
        cpa16(sb + SM_VL0 + (uint32_t)buf * 8192u + voff, vl + (size_t)d * NPIX + c0 + ch * 8);
    }
}

// ============================================================================
// Kernel 2: HMMA flash attention (no-max softmax; theta pre-scaled by log2e
// so p = ex2(s)). 128 threads / 4 warps = 2 row-groups x 2 col-groups;
// warp tile 32x32. Split-bf16 3-term for both GEMMs. BM=64 -> 400 CTAs,
// occ 2-3 CTAs/SM: cross-CTA overlap hides exp/pack bubbles.
// ============================================================================
__global__ void __launch_bounds__(128, 2) attn_kernel()
{
    extern __shared__ char smem[];
    uint32_t sb = sptr(smem);
    int tid = threadIdx.x;
    int w = tid >> 5, lid = tid & 31;
    int rg = w >> 1, cg = w & 1;
    int gid = lid >> 2, tig = lid & 3;
    int b = blockIdx.y;
    int n0pix = blockIdx.x * BM;

    const __nv_bfloat16* tq = g_tqn + (size_t)b * NPIX * 64;
    const __nv_bfloat16* pq = g_pqn + (size_t)b * NPIX * 64;
    const __nv_bfloat16* vh = g_gxh + (size_t)b * CI * NPIX;
    const __nv_bfloat16* vl = g_gxl + (size_t)b * CI * NPIX;

    // ---- prologue: Q tile + first K/V tile ----
#pragma unroll
    for (int h = 0; h < 4; h++) {
        int id = tid + h * 128;
        int r = id >> 3, ch = id & 7;
        cpa16(sb + SM_Q + sw((uint32_t)(r * 128 + ch * 16)),
              tq + (size_t)(n0pix + r) * 64 + ch * 8);
    }
    load_kv(sb, 0, pq, vh, vl, 0, tid);
    cpa_commit();
    cpa_wait0();
    __syncthreads();

    // ---- Q fragments (persistent): [mb][kstep][4], hi bytes 0-63, lo 64-127
    uint32_t qh[2][2][4], ql[2][2][4];
#pragma unroll
    for (int mb = 0; mb < 2; mb++) {
        uint32_t rowb = (uint32_t)(rg * 32 + mb * 16 + (lid & 15)) * 128 + (uint32_t)((lid >> 4) * 16);
#pragma unroll
        for (int ks = 0; ks < 2; ks++) {
            ldsm4(qh[mb][ks], sb + SM_Q + sw(rowb + (uint32_t)(ks * 32)));
            ldsm4(ql[mb][ks], sb + SM_Q + sw(rowb + (uint32_t)(64 + ks * 32)));
        }
    }

    float o[2][4][4];
    float lsum[2][2];
#pragma unroll
    for (int mb = 0; mb < 2; mb++) {
        lsum[mb][0] = 0.0f; lsum[mb][1] = 0.0f;
#pragma unroll
        for (int dn = 0; dn < 4; dn++)
#pragma unroll
            for (int e = 0; e < 4; e++) o[mb][dn][e] = 0.0f;
    }

    uint32_t blane = (uint32_t)((lid & 7) * 128 + (lid >> 3) * 16);

    for (int it = 0; it < NT; it++) {
        int buf = it & 1;
        if (it + 1 < NT) load_kv(sb, buf ^ 1, pq, vh, vl, (it + 1) * BN, tid);
        cpa_commit();

        uint32_t kb  = sb + SM_K0  + (uint32_t)buf * 8192u;
        uint32_t vhb = sb + SM_VH0 + (uint32_t)buf * 8192u;
        uint32_t vlb = sb + SM_VL0 + (uint32_t)buf * 8192u;

        // ---- S = Q K^T (split-bf16, 3 terms) ----
        float sa[2][4][4];
#pragma unroll
        for (int mb = 0; mb < 2; mb++)
#pragma unroll
            for (int j = 0; j < 4; j++)
#pragma unroll
                for (int e = 0; e < 4; e++) sa[mb][j][e] = 0.0f;

#pragma unroll
        for (int j = 0; j < 4; j++) {
            uint32_t nrow = (uint32_t)((cg * 32 + j * 8) * 128);
            uint32_t kh[4], klr[4];
            ldsm4(kh,  kb + sw(nrow + blane));
            ldsm4(klr, kb + sw(nrow + 64u + blane));
#pragma unroll
            for (int mb = 0; mb < 2; mb++) {
                mma16816(sa[mb][j], qh[mb][0], kh[0],  kh[1]);
                mma16816(sa[mb][j], qh[mb][1], kh[2],  kh[3]);
                mma16816(sa[mb][j], qh[mb][0], klr[0], klr[1]);
                mma16816(sa[mb][j], qh[mb][1], klr[2], klr[3]);
                mma16816(sa[mb][j], ql[mb][0], kh[0],  kh[1]);
                mma16816(sa[mb][j], ql[mb][1], kh[2],  kh[3]);
            }
        }

        // ---- P = ex2(S); pack split-bf16 A-fragments in registers ----
        uint32_t ph[2][2][4], pl[2][2][4];
#pragma unroll
        for (int mb = 0; mb < 2; mb++) {
#pragma unroll
            for (int j = 0; j < 4; j++) {
                float p0 = ex2(sa[mb][j][0]);
                float p1 = ex2(sa[mb][j][1]);
                float p2 = ex2(sa[mb][j][2]);
                float p3 = ex2(sa[mb][j][3]);
                lsum[mb][0] += p0 + p1;
                lsum[mb][1] += p2 + p3;
                int kc = j >> 1, rbase = (j & 1) * 2;
                uint32_t h0 = bf16x2(p0, p1);
                uint32_t h1 = bf16x2(p2, p3);
                ph[mb][kc][rbase]     = h0;
                ph[mb][kc][rbase + 1] = h1;
                float h0a = __uint_as_float(h0 << 16);
                float h0b = __uint_as_float(h0 & 0xffff0000u);
                float h1a = __uint_as_float(h1 << 16);
                float h1b = __uint_as_float(h1 & 0xffff0000u);
                pl[mb][kc][rbase]     = bf16x2(p0 - h0a, p1 - h0b);
                pl[mb][kc][rbase + 1] = bf16x2(p2 - h1a, p3 - h1b);
            }
        }

        // ---- O += P V (warp's k-range = m cols cg*32..+31 = bytes cg*64..) --
#pragma unroll
        for (int dn = 0; dn < 4; dn++) {
            uint32_t drow = (uint32_t)(dn * 8 * 128 + cg * 64);
            uint32_t vhf[4], vlf[4];
            ldsm4(vhf, vhb + sw(drow + blane));
            ldsm4(vlf, vlb + sw(drow + blane));
#pragma unroll
            for (int mb = 0; mb < 2; mb++) {
                mma16816(o[mb][dn], ph[mb][0], vhf[0], vhf[1]);
                mma16816(o[mb][dn], ph[mb][1], vhf[2], vhf[3]);
                mma16816(o[mb][dn], ph[mb][0], vlf[0], vlf[1]);
                mma16816(o[mb][dn], ph[mb][1], vlf[2], vlf[3]);
                mma16816(o[mb][dn], pl[mb][0], vhf[0], vhf[1]);
                mma16816(o[mb][dn], pl[mb][1], vhf[2], vhf[3]);
            }
        }

        cpa_wait0();
        __syncthreads();
    }

    // ---- epilogue: reduce l (quad + cross-cg), combine O halves ----
    float* larr = (float*)(smem + SM_MISC);          // [2 cg][64]
    float* os   = (float*)(smem + SM_K0);            // [2 cg][32 d][64 r]

#pragma unroll
    for (int mb = 0; mb < 2; mb++) {
#pragma unroll
        for (int hf = 0; hf < 2; hf++) {
            float v = lsum[mb][hf];
            v += __shfl_xor_sync(0xffffffffu, v, 1);
            v += __shfl_xor_sync(0xffffffffu, v, 2);
            if (tig == 0)
                larr[cg * 64 + rg * 32 + mb * 16 + gid + 8 * hf] = v;
        }
    }

    float* osp = os + cg * 32 * 64;
#pragma unroll
    for (int mb = 0; mb < 2; mb++) {
        int row0 = rg * 32 + mb * 16 + gid;
#pragma unroll
        for (int dn = 0; dn < 4; dn++) {
            int d0 = dn * 8 + tig * 2;
            osp[d0 * 64 + row0]           = o[mb][dn][0];
            osp[(d0 + 1) * 64 + row0]     = o[mb][dn][1];
            osp[d0 * 64 + row0 + 8]       = o[mb][dn][2];
            osp[(d0 + 1) * 64 + row0 + 8] = o[mb][dn][3];
        }
    }
    __syncthreads();

    float* y = g_y + (size_t)b * CI * NPIX;
#pragma unroll
    for (int h = 0; h < 16; h++) {
        int idx = tid + h * 128;
        int d = idx >> 6, r = idx & 63;
        float denom = larr[r] + larr[64 + r];
        float num = os[d * 64 + r] + os[32 * 64 + d * 64 + r];
        y[(size_t)d * NPIX + n0pix + r] = num / denom;
    }
}

// ============================================================================
// Kernel 3: out conv (32->64) + BN (folded) + residual.
// grid (50, 4, 2): z selects 32 of 64 output channels.
// ============================================================================
__global__ void __launch_bounds__(128) back_kernel(
    const float* __restrict__ x,
    const float* __restrict__ w_out, const float* __restrict__ b_out,
    const float* __restrict__ gamma, const float* __restrict__ beta,
    const float* __restrict__ mean,  const float* __restrict__ var,
    float* __restrict__ out)
{
    __shared__ float ws[32][CI];
    __shared__ float invs[32], shift[32];
    int tid = threadIdx.x;
    int co0 = blockIdx.z * 32;

    for (int i = tid; i < 32 * CI; i += 128) ws[i / CI][i % CI] = w_out[co0 * CI + i];
    if (tid < 32) {
        int co = co0 + tid;
        float inv = gamma[co] * rsqrtf(var[co] + 1e-4f);
        invs[tid]  = inv;
        shift[tid] = beta[co] + (b_out[co] - mean[co]) * inv;
    }
    __syncthreads();

    int b = blockIdx.y;
    int n = blockIdx.x * 128 + tid;

    ull yr2[CI / 2];
#pragma unroll
    for (int d2 = 0; d2 < CI / 2; d2++) {
        float a = g_y[(size_t)(b * CI + 2 * d2)     * NPIX + n];
        float c = g_y[(size_t)(b * CI + 2 * d2 + 1) * NPIX + n];
        yr2[d2] = pack2(a, c);
    }

#pragma unroll
    for (int cl = 0; cl < 32; cl++) {
        const ull* wrow = (const ull*)&ws[cl][0];
        ull acc2 = 0ull;
#pragma unroll
        for (int d2 = 0; d2 < CI / 2; d2++) acc2 = ffma2(wrow[d2], yr2[d2], acc2);
        float hi, lo; unpack2(acc2, lo, hi);
        int idx = (b * NC + co0 + cl) * NPIX + n;
        out[idx] = (lo + hi) * invs[cl] + shift[cl] + x[idx];
    }
}

// ============================================================================
extern "C" void kernel_launch(void* const* d_in, const int* in_sizes, int n_in,
                              void* d_out, int out_size)
{
    const float* x       = (const float*)d_in[0];
    const float* w_theta = (const float*)d_in[1];
    const float* b_theta = (const float*)d_in[2];
    const float* w_phi   = (const float*)d_in[3];
    const float* b_phi   = (const float*)d_in[4];
    const float* w_g     = (const float*)d_in[5];
    const float* b_g     = (const float*)d_in[6];
    const float* w_out   = (const float*)d_in[7];
    const float* b_out   = (const float*)d_in[8];
    const float* bn_g    = (const float*)d_in[9];
    const float* bn_b    = (const float*)d_in[10];
    const float* bn_m    = (const float*)d_in[11];
    const float* bn_v    = (const float*)d_in[12];
    float* out = (float*)d_out;

    static bool attr_set = false;
    if (!attr_set) {
        cudaFuncSetAttribute(attn_kernel, cudaFuncAttributeMaxDynamicSharedMemorySize, SMEM_TOTAL);
        attr_set = true;
    }

    front_kernel<<<dim3((BATCH * NPIX) / 128, 3), 128>>>(x, w_theta, b_theta, w_phi, b_phi, w_g, b_g);
    attn_kernel<<<dim3(NPIX / BM, BATCH), 128, SMEM_TOTAL>>>();
    back_kernel<<<dim3(NPIX / 128, BATCH, 2), 128>>>(x, w_out, b_out, bn_g, bn_b, bn_m, bn_v, out);
}

// round 15
// speedup vs baseline: 1.1639x; 1.1639x over previous
#include <cuda_runtime.h>
#include <cuda_bf16.h>
#include <cstdint>

typedef unsigned long long ull;

#define BATCH 4
#define NC    64
#define CI    32
#define NPIX  6400
#define BM    128           // q rows per CTA
#define NT2   (NPIX / 128)  // 50 double-tiles (128 k-cols each)
#define LOG2E 1.4426950408889634f

// ---------------- scratch (__device__ globals; no allocs allowed) ----------
__device__ __align__(1024) __nv_bfloat16 g_tqn[BATCH * NPIX * 64]; // theta*log2e: [b][n][hi32|lo32]
__device__ __align__(1024) __nv_bfloat16 g_pqn[BATCH * NPIX * 64]; // phi:         [b][n][hi32|lo32]
__device__ __align__(1024) __nv_bfloat16 g_gxh[BATCH * CI * NPIX]; // g hi:  [b][d][n]
__device__ __align__(1024) __nv_bfloat16 g_gxl[BATCH * CI * NPIX]; // g lo:  [b][d][n]
__device__ float g_y[BATCH * CI * NPIX];                           // attention out [b][d][n]

// ---------------- small helpers -------------------------------------------
__device__ __forceinline__ ull ffma2(ull a, ull b, ull c) {
    ull d; asm("fma.rn.f32x2 %0, %1, %2, %3;" : "=l"(d) : "l"(a), "l"(b), "l"(c)); return d;
}
__device__ __forceinline__ ull pack2(float lo, float hi) {
    ull d; asm("mov.b64 %0, {%1, %2};" : "=l"(d) : "f"(lo), "f"(hi)); return d;
}
__device__ __forceinline__ void unpack2(ull v, float& lo, float& hi) {
    asm("mov.b64 {%0, %1}, %2;" : "=f"(lo), "=f"(hi) : "l"(v));
}
// packed bf16x2: low half <- lo, high half <- hi
__device__ __forceinline__ uint32_t bf16x2(float lo, float hi) {
    uint32_t r; asm("cvt.rn.bf16x2.f32 %0, %1, %2;" : "=r"(r) : "f"(hi), "f"(lo)); return r;
}
__device__ __forceinline__ float ex2(float x) {
    float r; asm("ex2.approx.f32 %0, %1;" : "=f"(r) : "f"(x)); return r;
}
__device__ __forceinline__ uint32_t sptr(const void* p) {
    return (uint32_t)__cvta_generic_to_shared(p);
}
__device__ __forceinline__ void cpa16(uint32_t dst, const void* src) {
    asm volatile("cp.async.cg.shared.global [%0], [%1], 16;" :: "r"(dst), "l"(src));
}
__device__ __forceinline__ void cpa_commit() { asm volatile("cp.async.commit_group;" ::: "memory"); }
__device__ __forceinline__ void cpa_wait0()  { asm volatile("cp.async.wait_group 0;"  ::: "memory"); }
__device__ __forceinline__ uint32_t sw(uint32_t o) { return o ^ ((o >> 3) & 0x70); } // SW128

__device__ __forceinline__ void ldsm4(uint32_t* r, uint32_t addr) {
    asm volatile("ldmatrix.sync.aligned.m8n8.x4.shared.b16 {%0,%1,%2,%3}, [%4];"
                 : "=r"(r[0]), "=r"(r[1]), "=r"(r[2]), "=r"(r[3]) : "r"(addr));
}
__device__ __forceinline__ void mma16816(float* d, const uint32_t* a,
                                         uint32_t b0, uint32_t b1) {
    asm volatile(
        "mma.sync.aligned.m16n8k16.row.col.f32.bf16.bf16.f32 "
        "{%0,%1,%2,%3}, {%4,%5,%6,%7}, {%8,%9}, {%0,%1,%2,%3};"
        : "+f"(d[0]), "+f"(d[1]), "+f"(d[2]), "+f"(d[3])
        : "r"(a[0]), "r"(a[1]), "r"(a[2]), "r"(a[3]), "r"(b0), "r"(b1));
}

// ---------------- SMEM map -------------------------------------------------
#define SM_Q    0u       // 128 rows x 128B (hi|lo)                    16384
#define SM_K0   16384u   // 128 x 128B per buf (2 subtiles), stride 16384 (x2)
#define SM_VH0  49152u   // [sub][32 x 128B] per buf, stride 8192      (x2)
#define SM_VL0  65536u
#define SM_MISC 81920u   // larr: 2 x 128 floats = 1KB
#define SMEM_TOTAL (81920 + 1024)
// epilogue reuses SM_K0..SM_K0+32KB as os[2][32][128] floats

// ============================================================================
// Kernel 1: 1x1 convs -> bf16 hi/lo. theta pre-scaled by log2(e).
// theta/phi: [n][hi32|lo32] 128B rows; g: d-major hi/lo planes.
// All global stores staged through smem -> fully coalesced 16B chunks.
// ============================================================================
__global__ void __launch_bounds__(128) front_kernel(
    const float* __restrict__ x,
    const float* __restrict__ wt, const float* __restrict__ bt,
    const float* __restrict__ wp, const float* __restrict__ bp,
    const float* __restrict__ wg, const float* __restrict__ bg)
{
    __shared__ float ws[3][CI][NC];
    __shared__ float bs[3][CI];
    __shared__ uint4 st[128][8];          // 16KB staging (union of uses)
    int tid = threadIdx.x;
    for (int i = tid; i < 3 * CI * NC; i += 128) {
        int m = i / (CI * NC), r = i % (CI * NC);
        const float* w = (m == 0) ? wt : ((m == 1) ? wp : wg);
        float sc = (m == 0) ? LOG2E : 1.0f;
        ws[m][r / NC][r % NC] = w[r] * sc;
    }
    if (tid < 3 * CI) {
        int m = tid / CI, o = tid % CI;
        bs[m][o] = ((m == 0) ? bt[o] * LOG2E : ((m == 1) ? bp[o] : bg[o]));
    }
    __syncthreads();

    int gn = blockIdx.x * 128 + tid;
    int b = gn / NPIX, n = gn % NPIX;
    int n0 = (blockIdx.x * 128) % NPIX;   // block-contiguous pixel base

    ull xr2[NC / 2];
#pragma unroll
    for (int c2 = 0; c2 < NC / 2; c2++) {
        float a = x[(b * NC + 2 * c2)     * NPIX + n];
        float c = x[(b * NC + 2 * c2 + 1) * NPIX + n];
        xr2[c2] = pack2(a, c);
    }

#pragma unroll
    for (int m = 0; m < 3; m++) {
        float v[CI];
#pragma unroll
        for (int o = 0; o < CI; o++) {
            const ull* wrow = (const ull*)&ws[m][o][0];
            ull acc2 = 0ull;
#pragma unroll
            for (int c2 = 0; c2 < NC / 2; c2++) acc2 = ffma2(wrow[c2], xr2[c2], acc2);
            float hi, lo; unpack2(acc2, lo, hi);
            v[o] = bs[m][o] + lo + hi;
        }

        if (m < 2) {
            // build hi|lo row (8 x uint4), stage swizzled, store coalesced
#pragma unroll
            for (int q = 0; q < 8; q++) {
                uint32_t wds[4];
#pragma unroll
                for (int e = 0; e < 4; e++) {
                    if (q < 4) {
                        int o2 = q * 4 + e;             // hi words 0..15
                        float a = v[2 * o2], c = v[2 * o2 + 1];
                        wds[e] = bf16x2(a, c);
                    } else {
                        int o2 = (q - 4) * 4 + e;       // lo words 0..15
                        float a = v[2 * o2], c = v[2 * o2 + 1];
                        uint32_t hp = bf16x2(a, c);
                        float ha = __uint_as_float(hp << 16);
                        float hc = __uint_as_float(hp & 0xffff0000u);
                        wds[e] = bf16x2(a - ha, c - hc);
                    }
                }
                st[tid][q ^ (tid & 7)] = make_uint4(wds[0], wds[1], wds[2], wds[3]);
            }
            __syncthreads();
            __nv_bfloat16* base = ((m == 0) ? g_tqn : g_pqn) + (size_t)(b * NPIX + n0) * 64;
#pragma unroll
            for (int h = 0; h < 8; h++) {
                int id = tid + h * 128;                 // 0..1023
                int pix = id >> 3, ch = id & 7;
                ((uint4*)base)[pix * 8 + ch] = st[pix][ch ^ (pix & 7)];
            }
            __syncthreads();
        } else {
            // g: stage hi/lo planes [2][32][128] bf16 in st (16KB)
            __nv_bfloat16* gst = (__nv_bfloat16*)st;
#pragma unroll
            for (int o = 0; o < CI; o++) {
                __nv_bfloat16 h = __float2bfloat16(v[o]);
                gst[o * 128 + tid] = h;
                gst[CI * 128 + o * 128 + tid] = __float2bfloat16(v[o] - __bfloat162float(h));
            }
            __syncthreads();
#pragma unroll
            for (int h = 0; h < 8; h++) {
                int id = tid + h * 128;                 // 0..1023
                int plane = id >> 9, o = (id >> 4) & 31, ch = id & 15;
                __nv_bfloat16* dst = (plane ? g_gxl : g_gxh) + (size_t)(b * CI + o) * NPIX + n0 + ch * 8;
                *(uint4*)dst = ((uint4*)gst)[(plane * CI + o) * 16 + ch];
            }
        }
    }
}

// ---------------- 128-col K/V block loader (cp.async, SW128 dst) -----------
__device__ __forceinline__ void load_kv128(uint32_t sb, int buf,
                                           const __nv_bfloat16* pq,
                                           const __nv_bfloat16* vh,
                                           const __nv_bfloat16* vl,
                                           int c0, int tid)
{
    uint32_t kbase = sb + SM_K0 + (uint32_t)buf * 16384u;
#pragma unroll
    for (int h = 0; h < 4; h++) {
        int id = tid + h * 256;                 // 0..1023
        int k = id >> 3, ch = id & 7;
        cpa16(kbase + sw((uint32_t)(k * 128 + ch * 16)),
              pq + (size_t)(c0 + k) * 64 + ch * 8);
    }
#pragma unroll
    for (int h = 0; h < 2; h++) {
        int id = tid + h * 256;                 // 0..511
        int s = id >> 8, d = (id >> 3) & 31, ch = id & 7;
        uint32_t voff = (uint32_t)(s * 4096) + sw((uint32_t)(d * 128 + ch * 16));
        const __nv_bfloat16* srch = vh + (size_t)d * NPIX + c0 + s * 64 + ch * 8;
        const __nv_bfloat16* srcl = vl + (size_t)d * NPIX + c0 + s * 64 + ch * 8;
        cpa16(sb + SM_VH0 + (uint32_t)buf * 8192u + voff, srch);
        cpa16(sb + SM_VL0 + (uint32_t)buf * 8192u + voff, srcl);
    }
}

// ============================================================================
// Kernel 2: HMMA flash attention (no-max softmax; theta pre-scaled -> ex2).
// 256 threads / 8 warps = 4 row-groups x 2 col-groups; warp tile 32x32.
// Two 64-col subtiles per loop iter: ONE sync + ONE cp.async wait per 128 cols.
// Split-bf16 3-term for both GEMMs; P stays in registers.
// ============================================================================
__global__ void __launch_bounds__(256) attn_kernel()
{
    extern __shared__ char smem[];
    uint32_t sb = sptr(smem);
    int tid = threadIdx.x;
    int w = tid >> 5, lid = tid & 31;
    int rg = w >> 1, cg = w & 1;
    int gid = lid >> 2, tig = lid & 3;
    int b = blockIdx.y;
    int n0pix = blockIdx.x * BM;

    const __nv_bfloat16* tq = g_tqn + (size_t)b * NPIX * 64;
    const __nv_bfloat16* pq = g_pqn + (size_t)b * NPIX * 64;
    const __nv_bfloat16* vh = g_gxh + (size_t)b * CI * NPIX;
    const __nv_bfloat16* vl = g_gxl + (size_t)b * CI * NPIX;

    // ---- prologue: Q tile + first 128-col K/V block ----
#pragma unroll
    for (int h = 0; h < 4; h++) {
        int id = tid + h * 256;
        int r = id >> 3, ch = id & 7;
        cpa16(sb + SM_Q + sw((uint32_t)(r * 128 + ch * 16)),
              tq + (size_t)(n0pix + r) * 64 + ch * 8);
    }
    load_kv128(sb, 0, pq, vh, vl, 0, tid);
    cpa_commit();
    cpa_wait0();
    __syncthreads();

    // ---- Q fragments (persistent) ----
    uint32_t qh[2][2][4], ql[2][2][4];
#pragma unroll
    for (int mb = 0; mb < 2; mb++) {
        uint32_t rowb = (uint32_t)(rg * 32 + mb * 16 + (lid & 15)) * 128 + (uint32_t)((lid >> 4) * 16);
#pragma unroll
        for (int ks = 0; ks < 2; ks++) {
            ldsm4(qh[mb][ks], sb + SM_Q + sw(rowb + (uint32_t)(ks * 32)));
            ldsm4(ql[mb][ks], sb + SM_Q + sw(rowb + (uint32_t)(64 + ks * 32)));
        }
    }

    float o[2][4][4];
    float lsum[2][2];
#pragma unroll
    for (int mb = 0; mb < 2; mb++) {
        lsum[mb][0] = 0.0f; lsum[mb][1] = 0.0f;
#pragma unroll
        for (int dn = 0; dn < 4; dn++)
#pragma unroll
            for (int e = 0; e < 4; e++) o[mb][dn][e] = 0.0f;
    }

    uint32_t blane = (uint32_t)((lid & 7) * 128 + (lid >> 3) * 16);

    for (int it = 0; it < NT2; it++) {
        int buf = it & 1;
        if (it + 1 < NT2) load_kv128(sb, buf ^ 1, pq, vh, vl, (it + 1) * 128, tid);
        cpa_commit();

#pragma unroll
        for (int sub = 0; sub < 2; sub++) {
            uint32_t kb  = sb + SM_K0  + (uint32_t)buf * 16384u + (uint32_t)sub * 8192u;
            uint32_t vhb = sb + SM_VH0 + (uint32_t)buf * 8192u  + (uint32_t)sub * 4096u;
            uint32_t vlb = sb + SM_VL0 + (uint32_t)buf * 8192u  + (uint32_t)sub * 4096u;

            // ---- S = Q K^T (split-bf16, 3 terms) ----
            float sa[2][4][4];
#pragma unroll
            for (int mb = 0; mb < 2; mb++)
#pragma unroll
                for (int j = 0; j < 4; j++)
#pragma unroll
                    for (int e = 0; e < 4; e++) sa[mb][j][e] = 0.0f;

#pragma unroll
            for (int j = 0; j < 4; j++) {
                uint32_t nrow = (uint32_t)((cg * 32 + j * 8) * 128);
                uint32_t kh[4], klr[4];
                ldsm4(kh,  kb + sw(nrow + blane));
                ldsm4(klr, kb + sw(nrow + 64u + blane));
#pragma unroll
                for (int mb = 0; mb < 2; mb++) {
                    mma16816(sa[mb][j], qh[mb][0], kh[0],  kh[1]);
                    mma16816(sa[mb][j], qh[mb][1], kh[2],  kh[3]);
                    mma16816(sa[mb][j], qh[mb][0], klr[0], klr[1]);
                    mma16816(sa[mb][j], qh[mb][1], klr[2], klr[3]);
                    mma16816(sa[mb][j], ql[mb][0], kh[0],  kh[1]);
                    mma16816(sa[mb][j], ql[mb][1], kh[2],  kh[3]);
                }
            }

            // ---- P = ex2(S); pack split-bf16 A-fragments in registers ----
            uint32_t ph[2][2][4], pl[2][2][4];
#pragma unroll
            for (int mb = 0; mb < 2; mb++) {
#pragma unroll
                for (int j = 0; j < 4; j++) {
                    float p0 = ex2(sa[mb][j][0]);
                    float p1 = ex2(sa[mb][j][1]);
                    float p2 = ex2(sa[mb][j][2]);
                    float p3 = ex2(sa[mb][j][3]);
                    lsum[mb][0] += p0 + p1;
                    lsum[mb][1] += p2 + p3;
                    int kc = j >> 1, rbase = (j & 1) * 2;
                    uint32_t h0 = bf16x2(p0, p1);
                    uint32_t h1 = bf16x2(p2, p3);
                    ph[mb][kc][rbase]     = h0;
                    ph[mb][kc][rbase + 1] = h1;
                    float h0a = __uint_as_float(h0 << 16);
                    float h0b = __uint_as_float(h0 & 0xffff0000u);
                    float h1a = __uint_as_float(h1 << 16);
                    float h1b = __uint_as_float(h1 & 0xffff0000u);
                    pl[mb][kc][rbase]     = bf16x2(p0 - h0a, p1 - h0b);
                    pl[mb][kc][rbase + 1] = bf16x2(p2 - h1a, p3 - h1b);
                }
            }

            // ---- O += P V ----
#pragma unroll
            for (int dn = 0; dn < 4; dn++) {
                uint32_t drow = (uint32_t)(dn * 8 * 128 + cg * 64);
                uint32_t vhf[4], vlf[4];
                ldsm4(vhf, vhb + sw(drow + blane));
                ldsm4(vlf, vlb + sw(drow + blane));
#pragma unroll
                for (int mb = 0; mb < 2; mb++) {
                    mma16816(o[mb][dn], ph[mb][0], vhf[0], vhf[1]);
                    mma16816(o[mb][dn], ph[mb][1], vhf[2], vhf[3]);
                    mma16816(o[mb][dn], ph[mb][0], vlf[0], vlf[1]);
                    mma16816(o[mb][dn], ph[mb][1], vlf[2], vlf[3]);
                    mma16816(o[mb][dn], pl[mb][0], vhf[0], vhf[1]);
                    mma16816(o[mb][dn], pl[mb][1], vhf[2], vhf[3]);
                }
            }
        }

        cpa_wait0();
        __syncthreads();   // one barrier per 128 cols
    }

    // ---- epilogue: reduce l (quad + cross-cg), combine O halves ----
    float* larr = (float*)(smem + SM_MISC);          // [2 cg][128]
    float* os   = (float*)(smem + SM_K0);            // [2 cg][32 d][128 r]

#pragma unroll
    for (int mb = 0; mb < 2; mb++) {
#pragma unroll
        for (int hf = 0; hf < 2; hf++) {
            float v = lsum[mb][hf];
            v += __shfl_xor_sync(0xffffffffu, v, 1);
            v += __shfl_xor_sync(0xffffffffu, v, 2);
            if (tig == 0)
                larr[cg * 128 + rg * 32 + mb * 16 + gid + 8 * hf] = v;
        }
    }

    float* osp = os + cg * 32 * 128;
#pragma unroll
    for (int mb = 0; mb < 2; mb++) {
        int row0 = rg * 32 + mb * 16 + gid;
#pragma unroll
        for (int dn = 0; dn < 4; dn++) {
            int d0 = dn * 8 + tig * 2;
            osp[d0 * 128 + row0]           = o[mb][dn][0];
            osp[(d0 + 1) * 128 + row0]     = o[mb][dn][1];
            osp[d0 * 128 + row0 + 8]       = o[mb][dn][2];
            osp[(d0 + 1) * 128 + row0 + 8] = o[mb][dn][3];
        }
    }
    __syncthreads();

    float* y = g_y + (size_t)b * CI * NPIX;
#pragma unroll
    for (int h = 0; h < 16; h++) {
        int idx = tid + h * 256;
        int d = idx >> 7, r = idx & 127;
        float denom = larr[r] + larr[128 + r];
        float num = os[d * 128 + r] + os[32 * 128 + d * 128 + r];
        y[(size_t)d * NPIX + n0pix + r] = num / denom;
    }
}

// ============================================================================
// Kernel 3: out conv (32->64) + BN (folded) + residual.
// grid (50, 4, 2): z selects 32 of 64 output channels.
// ============================================================================
__global__ void __launch_bounds__(128) back_kernel(
    const float* __restrict__ x,
    const float* __restrict__ w_out, const float* __restrict__ b_out,
    const float* __restrict__ gamma, const float* __restrict__ beta,
    const float* __restrict__ mean,  const float* __restrict__ var,
    float* __restrict__ out)
{
    __shared__ float ws[32][CI];
    __shared__ float invs[32], shift[32];
    int tid = threadIdx.x;
    int co0 = blockIdx.z * 32;

    for (int i = tid; i < 32 * CI; i += 128) ws[i / CI][i % CI] = w_out[co0 * CI + i];
    if (tid < 32) {
        int co = co0 + tid;
        float inv = gamma[co] * rsqrtf(var[co] + 1e-4f);
        invs[tid]  = inv;
        shift[tid] = beta[co] + (b_out[co] - mean[co]) * inv;
    }
    __syncthreads();

    int b = blockIdx.y;
    int n = blockIdx.x * 128 + tid;

    ull yr2[CI / 2];
#pragma unroll
    for (int d2 = 0; d2 < CI / 2; d2++) {
        float a = g_y[(size_t)(b * CI + 2 * d2)     * NPIX + n];
        float c = g_y[(size_t)(b * CI + 2 * d2 + 1) * NPIX + n];
        yr2[d2] = pack2(a, c);
    }

#pragma unroll
    for (int cl = 0; cl < 32; cl++) {
        const ull* wrow = (const ull*)&ws[cl][0];
        ull acc2 = 0ull;
#pragma unroll
        for (int d2 = 0; d2 < CI / 2; d2++) acc2 = ffma2(wrow[d2], yr2[d2], acc2);
        float hi, lo; unpack2(acc2, lo, hi);
        int idx = (b * NC + co0 + cl) * NPIX + n;
        out[idx] = (lo + hi) * invs[cl] + shift[cl] + x[idx];
    }
}

// ============================================================================
extern "C" void kernel_launch(void* const* d_in, const int* in_sizes, int n_in,
                              void* d_out, int out_size)
{
    const float* x       = (const float*)d_in[0];
    const float* w_theta = (const float*)d_in[1];
    const float* b_theta = (const float*)d_in[2];
    const float* w_phi   = (const float*)d_in[3];
    const float* b_phi   = (const float*)d_in[4];
    const float* w_g     = (const float*)d_in[5];
    const float* b_g     = (const float*)d_in[6];
    const float* w_out   = (const float*)d_in[7];
    const float* b_out   = (const float*)d_in[8];
    const float* bn_g    = (const float*)d_in[9];
    const float* bn_b    = (const float*)d_in[10];
    const float* bn_m    = (const float*)d_in[11];
    const float* bn_v    = (const float*)d_in[12];
    float* out = (float*)d_out;

    static bool attr_set = false;
    if (!attr_set) {
        cudaFuncSetAttribute(attn_kernel, cudaFuncAttributeMaxDynamicSharedMemorySize, SMEM_TOTAL);
        attr_set = true;
    }

    front_kernel<<<(BATCH * NPIX) / 128, 128>>>(x, w_theta, b_theta, w_phi, b_phi, w_g, b_g);
    attn_kernel<<<dim3(NPIX / BM, BATCH), 256, SMEM_TOTAL>>>();
    back_kernel<<<dim3(NPIX / 128, BATCH, 2), 128>>>(x, w_out, b_out, bn_g, bn_b, bn_m, bn_v, out);
}